// round 5
// baseline (speedup 1.0000x reference)
#include <cuda_runtime.h>

#define FULL_MASK 0xffffffffu
#define DIM 768
#define NEXP 8
#define VEC (DIM / 4)          // 192 float4 per row
#define ROWS_PER_BLOCK 32
#define ITERS 8                // 8 iterations x 4 row-slots = 32 rows

__device__ __forceinline__ unsigned long long pack2(float a, float b) {
    unsigned long long p;
    asm("mov.b64 %0, {%1, %2};" : "=l"(p) : "f"(a), "f"(b));
    return p;
}
__device__ __forceinline__ void fma2(unsigned long long& acc,
                                     unsigned long long a,
                                     unsigned long long b) {
    asm("fma.rn.f32x2 %0, %1, %2, %0;" : "+l"(acc) : "l"(a), "l"(b));
}
__device__ __forceinline__ void unpack2(unsigned long long p, float& a, float& b) {
    asm("mov.b64 {%0, %1}, %2;" : "=f"(a), "=f"(b) : "l"(p));
}

__global__ __launch_bounds__(256)
void router_kernel(const float* __restrict__ x,
                   const float* __restrict__ W,
                   const float* __restrict__ bias,
                   float* __restrict__ out,
                   int nrows) {
    __shared__ float sh[ROWS_PER_BLOCK][NEXP];

    const int tid  = threadIdx.x;
    const int warp = tid >> 5;
    const int lane = tid & 31;
    const int slot = warp >> 1;   // row slot 0..3 within an iteration
    const int half = warp & 1;    // expert half: 0 -> e0..3, 1 -> e4..7
    const int rowBase = blockIdx.x * ROWS_PER_BLOCK;

    // ---- Load this warp's W slice into registers (4 experts x 24 cols/lane),
    //      packed as f32x2 pairs. 8 warps share the same 24KB W via L1. ----
    const float4* W4 = (const float4*)W;
    unsigned long long wpk[4][12];
    #pragma unroll
    for (int e = 0; e < 4; ++e) {
        #pragma unroll
        for (int c = 0; c < 6; ++c) {
            float4 w = __ldg(&W4[(half * 4 + e) * VEC + lane + 32 * c]);
            wpk[e][2 * c]     = pack2(w.x, w.y);
            wpk[e][2 * c + 1] = pack2(w.z, w.w);
        }
    }

    const float4* x4 = (const float4*)x;

    // Prefetch first row's x slice (6 coalesced LDG.128 per lane)
    float4 xv[6];
    {
        int row = rowBase + slot;
        if (row < nrows) {
            const float4* xr = x4 + (size_t)row * VEC + lane;
            #pragma unroll
            for (int c = 0; c < 6; ++c) xv[c] = __ldg(&xr[32 * c]);
        }
    }

    #pragma unroll
    for (int i = 0; i < ITERS; ++i) {
        // Pack current row's x into f32x2 pairs
        unsigned long long xp[12];
        #pragma unroll
        for (int c = 0; c < 6; ++c) {
            xp[2 * c]     = pack2(xv[c].x, xv[c].y);
            xp[2 * c + 1] = pack2(xv[c].z, xv[c].w);
        }
        // Software pipeline: issue next row's loads before compute
        if (i < ITERS - 1) {
            int row = rowBase + (i + 1) * 4 + slot;
            if (row < nrows) {
                const float4* xr = x4 + (size_t)row * VEC + lane;
                #pragma unroll
                for (int c = 0; c < 6; ++c) xv[c] = __ldg(&xr[32 * c]);
            }
        }

        // 48 packed FMAs: 4 experts x 12 f32x2 pairs
        unsigned long long acc2[4] = {0ull, 0ull, 0ull, 0ull};
        #pragma unroll
        for (int j = 0; j < 12; ++j) {
            #pragma unroll
            for (int e = 0; e < 4; ++e) fma2(acc2[e], xp[j], wpk[e][j]);
        }

        float acc[4];
        #pragma unroll
        for (int e = 0; e < 4; ++e) {
            float lo, hi;
            unpack2(acc2[e], lo, hi);
            acc[e] = lo + hi;
        }

        // Butterfly reduce 4 partial logits across the warp (20 SHFL)
        #pragma unroll
        for (int off = 16; off; off >>= 1) {
            #pragma unroll
            for (int e = 0; e < 4; ++e)
                acc[e] += __shfl_xor_sync(FULL_MASK, acc[e], off);
        }

        if (lane == 0) {
            #pragma unroll
            for (int e = 0; e < 4; ++e)
                sh[i * 4 + slot][half * 4 + e] = acc[e];
        }
    }

    __syncthreads();

    // ---- Epilogue: one thread per row -> bias + softmax + top-2 ----
    if (tid < ROWS_PER_BLOCK) {
        int row = rowBase + tid;
        if (row < nrows) {
            float l[NEXP];
            #pragma unroll
            for (int e = 0; e < NEXP; ++e) l[e] = sh[tid][e] + bias[e];

            // argmax (first occurrence on ties, matching jax.lax.top_k)
            int i1 = 0; float v1 = l[0];
            #pragma unroll
            for (int e = 1; e < NEXP; ++e)
                if (l[e] > v1) { v1 = l[e]; i1 = e; }
            int i2 = -1; float v2 = -3.0e38f;
            #pragma unroll
            for (int e = 0; e < NEXP; ++e)
                if (e != i1 && l[e] > v2) { v2 = l[e]; i2 = e; }

            float s = 0.0f;
            #pragma unroll
            for (int e = 0; e < NEXP; ++e) s += expf(l[e] - v1);
            float inv = 1.0f / s;
            float g1 = inv;                   // expf(v1 - v1) = 1
            float g2 = expf(v2 - v1) * inv;

            // Output: gates [nrows,2] first, then indices [nrows,2] as floats
            out[(size_t)row * 2]     = g1;
            out[(size_t)row * 2 + 1] = g2;
            float* oi = out + (size_t)nrows * 2;
            oi[(size_t)row * 2]     = (float)i1;
            oi[(size_t)row * 2 + 1] = (float)i2;
        }
    }
}

extern "C" void kernel_launch(void* const* d_in, const int* in_sizes, int n_in,
                              void* d_out, int out_size) {
    const float* x = (const float*)d_in[0];   // [128,197,768] fp32
    const float* W = (const float*)d_in[1];   // [8,768] fp32
    const float* b = (const float*)d_in[2];   // [8] fp32
    float* out = (float*)d_out;

    int nrows = in_sizes[0] / DIM;            // 128*197 = 25216
    int grid = (nrows + ROWS_PER_BLOCK - 1) / ROWS_PER_BLOCK;

    router_kernel<<<grid, 256>>>(x, W, b, out, nrows);
}

// round 6
// speedup vs baseline: 1.1747x; 1.1747x over previous
#include <cuda_runtime.h>

#define FULL_MASK 0xffffffffu
#define DIM 768
#define NEXP 8
#define VEC (DIM / 4)          // 192 float4 per row
#define HVEC (VEC / 2)         // 96 float4 per half-row
#define ROWS_PER_BLOCK 32
#define ITERS 16               // 16 iterations x 2 row-slots = 32 rows

__device__ __forceinline__ unsigned long long pack2(float a, float b) {
    unsigned long long p;
    asm("mov.b64 %0, {%1, %2};" : "=l"(p) : "f"(a), "f"(b));
    return p;
}
__device__ __forceinline__ void fma2(unsigned long long& acc,
                                     unsigned long long a,
                                     unsigned long long b) {
    asm("fma.rn.f32x2 %0, %1, %2, %0;" : "+l"(acc) : "l"(a), "l"(b));
}
__device__ __forceinline__ void unpack2(unsigned long long p, float& a, float& b) {
    asm("mov.b64 {%0, %1}, %2;" : "=f"(a), "=f"(b) : "l"(p));
}

__global__ __launch_bounds__(256, 2)
void router_kernel(const float* __restrict__ x,
                   const float* __restrict__ W,
                   const float* __restrict__ bias,
                   float* __restrict__ out,
                   int nrows) {
    // sh[row][dim_half][expert]
    __shared__ float sh[ROWS_PER_BLOCK][2][NEXP];

    const int tid   = threadIdx.x;
    const int warp  = tid >> 5;
    const int lane  = tid & 31;
    const int slot  = warp >> 2;        // row slot 0..1 within an iteration
    const int dhalf = (warp >> 1) & 1;  // dim half: cols [0,384) or [384,768)
    const int ehalf = warp & 1;         // expert half: e0..3 or e4..7
    const int rowBase = blockIdx.x * ROWS_PER_BLOCK;

    // ---- W slice in registers: 4 experts x 12 cols/lane (half-row) = 48 regs ----
    const float4* W4 = (const float4*)W;
    unsigned long long wpk[4][6];
    #pragma unroll
    for (int e = 0; e < 4; ++e) {
        #pragma unroll
        for (int c = 0; c < 3; ++c) {
            float4 w = __ldg(&W4[(ehalf * 4 + e) * VEC + dhalf * HVEC + lane + 32 * c]);
            wpk[e][2 * c]     = pack2(w.x, w.y);
            wpk[e][2 * c + 1] = pack2(w.z, w.w);
        }
    }

    const float4* xr = (const float4*)x + dhalf * HVEC + lane;

    // ---- Depth-2 software pipeline: two 3-float4 buffers ----
    float4 bufA[3], bufB[3];
    {
        int r0 = rowBase + slot;            // iter 0 row
        if (r0 < nrows) {
            const float4* p = xr + (size_t)r0 * VEC;
            #pragma unroll
            for (int c = 0; c < 3; ++c) bufA[c] = __ldg(&p[32 * c]);
        }
        int r1 = rowBase + 2 + slot;        // iter 1 row
        if (r1 < nrows) {
            const float4* p = xr + (size_t)r1 * VEC;
            #pragma unroll
            for (int c = 0; c < 3; ++c) bufB[c] = __ldg(&p[32 * c]);
        }
    }

    #pragma unroll
    for (int i = 0; i < ITERS; ++i) {
        float4* cur = (i & 1) ? bufB : bufA;

        // Pack current half-row into f32x2 pairs
        unsigned long long xp[6];
        #pragma unroll
        for (int c = 0; c < 3; ++c) {
            xp[2 * c]     = pack2(cur[c].x, cur[c].y);
            xp[2 * c + 1] = pack2(cur[c].z, cur[c].w);
        }

        // Prefetch row for iteration i+2 into the buffer just consumed
        if (i < ITERS - 2) {
            int row = rowBase + (i + 2) * 2 + slot;
            if (row < nrows) {
                const float4* p = xr + (size_t)row * VEC;
                #pragma unroll
                for (int c = 0; c < 3; ++c) cur[c] = __ldg(&p[32 * c]);
            }
        }

        // 24 packed FMAs: 4 experts x 6 f32x2 pairs
        unsigned long long acc2[4] = {0ull, 0ull, 0ull, 0ull};
        #pragma unroll
        for (int j = 0; j < 6; ++j) {
            #pragma unroll
            for (int e = 0; e < 4; ++e) fma2(acc2[e], xp[j], wpk[e][j]);
        }

        float acc[4];
        #pragma unroll
        for (int e = 0; e < 4; ++e) {
            float lo, hi;
            unpack2(acc2[e], lo, hi);
            acc[e] = lo + hi;
        }

        // Warp reduce 4 values in 12 SHFL:
        // stage xor16 on all 4, then lanes 0-15 reduce (e0,e1), lanes 16-31 (e2,e3)
        #pragma unroll
        for (int e = 0; e < 4; ++e)
            acc[e] += __shfl_xor_sync(FULL_MASK, acc[e], 16);
        float b0 = (lane < 16) ? acc[0] : acc[2];
        float b1 = (lane < 16) ? acc[1] : acc[3];
        #pragma unroll
        for (int off = 8; off; off >>= 1) {
            b0 += __shfl_xor_sync(FULL_MASK, b0, off);
            b1 += __shfl_xor_sync(FULL_MASK, b1, off);
        }

        if ((lane & 15) == 0) {
            int r = i * 2 + slot;
            int ebase = ehalf * 4 + (lane >> 4) * 2;
            sh[r][dhalf][ebase]     = b0;
            sh[r][dhalf][ebase + 1] = b1;
        }
    }

    __syncthreads();

    // ---- Epilogue: one thread per row -> combine halves + bias + softmax + top-2 ----
    if (tid < ROWS_PER_BLOCK) {
        int row = rowBase + tid;
        if (row < nrows) {
            float l[NEXP];
            #pragma unroll
            for (int e = 0; e < NEXP; ++e)
                l[e] = sh[tid][0][e] + sh[tid][1][e] + __ldg(&bias[e]);

            // top-1 / top-2 (first occurrence on ties, matching jax.lax.top_k)
            int i1 = 0; float v1 = l[0];
            #pragma unroll
            for (int e = 1; e < NEXP; ++e)
                if (l[e] > v1) { v1 = l[e]; i1 = e; }
            int i2 = -1; float v2 = -3.0e38f;
            #pragma unroll
            for (int e = 0; e < NEXP; ++e)
                if (e != i1 && l[e] > v2) { v2 = l[e]; i2 = e; }

            float s = 0.0f;
            #pragma unroll
            for (int e = 0; e < NEXP; ++e) s += expf(l[e] - v1);
            float inv = 1.0f / s;
            float g1 = inv;                   // expf(v1 - v1) = 1
            float g2 = expf(v2 - v1) * inv;

            // Output: gates [nrows,2] first, then indices [nrows,2] as floats
            out[(size_t)row * 2]     = g1;
            out[(size_t)row * 2 + 1] = g2;
            float* oi = out + (size_t)nrows * 2;
            oi[(size_t)row * 2]     = (float)i1;
            oi[(size_t)row * 2 + 1] = (float)i2;
        }
    }
}

extern "C" void kernel_launch(void* const* d_in, const int* in_sizes, int n_in,
                              void* d_out, int out_size) {
    const float* x = (const float*)d_in[0];   // [128,197,768] fp32
    const float* W = (const float*)d_in[1];   // [8,768] fp32
    const float* b = (const float*)d_in[2];   // [8] fp32
    float* out = (float*)d_out;

    int nrows = in_sizes[0] / DIM;            // 128*197 = 25216
    int grid = (nrows + ROWS_PER_BLOCK - 1) / ROWS_PER_BLOCK;

    router_kernel<<<grid, 256>>>(x, W, b, out, nrows);
}